// round 12
// baseline (speedup 1.0000x reference)
#include <cuda_runtime.h>
#include <cstdint>

#define BB   32
#define TT   128
#define KD   32
#define HH   4
#define DINP 160
#define HIDN 256

// Scratch + sync (static device globals; no allocation).
__device__ float g_act[BB * TT * DINP];     // [x | state]  4096 x 160
__device__ int   g_flag[BB];                // attn-producer arrival count per batch
__device__ int   g_qhead;                   // mlp work queue head
__device__ int   g_done;                    // CTA exit counter (for replay reset)

typedef unsigned long long ull;

__device__ __forceinline__ ull ffma2(ull a, ull b, ull c) {
    ull d;
    asm("fma.rn.f32x2 %0, %1, %2, %3;" : "=l"(d) : "l"(a), "l"(b), "l"(c));
    return d;
}
__device__ __forceinline__ ull pack2(float x, float y) {
    ull r;
    asm("mov.b64 %0, {%1, %2};" : "=l"(r) : "f"(x), "f"(y));
    return r;
}
__device__ __forceinline__ float2 unpack2(ull v) {
    float x, y;
    asm("mov.b64 {%0, %1}, %2;" : "=f"(x), "=f"(y) : "l"(v));
    return make_float2(x, y);
}
__device__ __forceinline__ void cpa16(uint32_t dst_smem, const void* src) {
    asm volatile("cp.async.cg.shared.global [%0], [%1], 16;\n"
                 :: "r"(dst_smem), "l"(src) : "memory");
}
__device__ __forceinline__ void cpa_commit() {
    asm volatile("cp.async.commit_group;\n" ::: "memory");
}
template <int N>
__device__ __forceinline__ void cpa_wait() {
    asm volatile("cp.async.wait_group %0;\n" :: "n"(N) : "memory");
}

// ---------------------------------------------------------------------------
// Attn-phase smem layout (floats). P aliases the proj staging region.
// ---------------------------------------------------------------------------
#define OFF_ST    0            // stateT [32][pitch 132]       4224
#define OFF_WQ    4224         // WqT-slice [32][pitch 68]     2176
#define OFF_WKV   6400         // Wk|Wv slice [32][pitch 68]   2176  (end 8576)
#define OFF_P     0            // P [128][64]                  8192  (alias)
#define OFF_KT    8576         // kT [32][128]                 4096
#define OFF_VT    12672        // vT [32][128]                 4096
#define OFF_QT    16768        // qT [32][64]                  2048
#define OFF_MX    18816        // [4][64]
#define OFF_SM    19072        // [4][64]
#define OFF_INV   19328        // [64]

// MLP-phase smem layout (same extern buffer, reused after attn phase)
#define CKP   8
#define MROWS 32
#define NRING 4
#define PANF  (CKP * HIDN)                    // 2048 floats / panel
#define NCH1  (DINP / CKP)                    // 20
#define NCHT  (NCH1 + HIDN / CKP)             // 52
#define MLP_SMEM_FLOATS (MROWS * DINP + MROWS * HIDN + NRING * PANF)  // 21504
#define FUSED_SMEM_BYTES (MLP_SMEM_FLOATS * 4)                        // 86016 (> attn 77568)

// ---------------------------------------------------------------------------
// Fused persistent kernel. grid 256 = (b, h, ihalf) attn items, 256 threads,
// 2 CTA/SM (all CTAs co-resident -> spin-waits are deadlock-free).
// ---------------------------------------------------------------------------
__global__ void __launch_bounds__(256, 2) fused_kernel(
    const float* __restrict__ state,
    const float* __restrict__ Wq,
    const float* __restrict__ Wk,
    const float* __restrict__ Wv,
    const float* __restrict__ W1, const float* __restrict__ b1,
    const float* __restrict__ W2, const float* __restrict__ b2,
    const float* __restrict__ Wo, const float* __restrict__ bo,
    float* __restrict__ out)
{
    extern __shared__ float sm[];
    __shared__ float s_red[MROWS][2];
    __shared__ int   s_idx;

    const int bx = blockIdx.x;
    const int t = threadIdx.x;

    // =======================================================================
    // PHASE A: fused QKV-proj + masked attention (identical math to R8-R11)
    // =======================================================================
    {
        const int b = bx >> 3, h = (bx >> 1) & 3, ihalf = bx & 1;
        const int ig0 = ihalf * 64;

        float* sT    = sm + OFF_ST;
        float* swq   = sm + OFF_WQ;
        float* swkv  = sm + OFF_WKV;
        float* P     = sm + OFF_P;
        float* kT    = sm + OFF_KT;
        float* vT    = sm + OFF_VT;
        float* qT    = sm + OFF_QT;
        float* s_mx  = sm + OFF_MX;
        float* s_sm  = sm + OFF_SM;
        float* s_inv = sm + OFF_INV;

        // ---- stage stateT [c][j] (pitch 132) and weight slices (pitch 68)
        {
            int r = t >> 1, c0 = (t & 1) * 16;
            const float4* p = (const float4*)(state + ((size_t)b * TT + r) * KD + c0);
            #pragma unroll
            for (int w = 0; w < 4; w++) {
                float4 v = p[w];
                sT[(c0 + 4 * w + 0) * 132 + r] = v.x;
                sT[(c0 + 4 * w + 1) * 132 + r] = v.y;
                sT[(c0 + 4 * w + 2) * 132 + r] = v.z;
                sT[(c0 + 4 * w + 3) * 132 + r] = v.w;
            }
        }
        {
            int r = t >> 3, q = t & 7;
            size_t src = (size_t)r * (KD * HH) + h * KD + q * 4;
            *(float4*)&swq[r * 68 + q * 4]        = *(const float4*)(Wq + src);
            *(float4*)&swkv[r * 68 + q * 4]       = *(const float4*)(Wk + src);
            *(float4*)&swkv[r * 68 + 32 + q * 4]  = *(const float4*)(Wv + src);
        }
        __syncthreads();

        // ---- KV projection: 128 rows x 64 cols (K|V), tile 8r x 4c
        {
            const int rg = t & 15, cg = t >> 4;
            const int j0 = rg * 8, c0 = cg * 4;
            ull acc[8][2];
            #pragma unroll
            for (int r = 0; r < 8; r++) { acc[r][0] = 0ull; acc[r][1] = 0ull; }

            #pragma unroll 8
            for (int k = 0; k < KD; k++) {
                float4 a0 = *(const float4*)&sT[k * 132 + j0];
                float4 a1 = *(const float4*)&sT[k * 132 + j0 + 4];
                ulonglong2 b2v = *(const ulonglong2*)&swkv[k * 68 + c0];
                ull ad;
                ad = pack2(a0.x, a0.x); acc[0][0] = ffma2(ad, b2v.x, acc[0][0]); acc[0][1] = ffma2(ad, b2v.y, acc[0][1]);
                ad = pack2(a0.y, a0.y); acc[1][0] = ffma2(ad, b2v.x, acc[1][0]); acc[1][1] = ffma2(ad, b2v.y, acc[1][1]);
                ad = pack2(a0.z, a0.z); acc[2][0] = ffma2(ad, b2v.x, acc[2][0]); acc[2][1] = ffma2(ad, b2v.y, acc[2][1]);
                ad = pack2(a0.w, a0.w); acc[3][0] = ffma2(ad, b2v.x, acc[3][0]); acc[3][1] = ffma2(ad, b2v.y, acc[3][1]);
                ad = pack2(a1.x, a1.x); acc[4][0] = ffma2(ad, b2v.x, acc[4][0]); acc[4][1] = ffma2(ad, b2v.y, acc[4][1]);
                ad = pack2(a1.y, a1.y); acc[5][0] = ffma2(ad, b2v.x, acc[5][0]); acc[5][1] = ffma2(ad, b2v.y, acc[5][1]);
                ad = pack2(a1.z, a1.z); acc[6][0] = ffma2(ad, b2v.x, acc[6][0]); acc[6][1] = ffma2(ad, b2v.y, acc[6][1]);
                ad = pack2(a1.w, a1.w); acc[7][0] = ffma2(ad, b2v.x, acc[7][0]); acc[7][1] = ffma2(ad, b2v.y, acc[7][1]);
            }

            float cs[4][8];
            #pragma unroll
            for (int r = 0; r < 8; r++) {
                float2 e0 = unpack2(acc[r][0]), e1 = unpack2(acc[r][1]);
                cs[0][r] = e0.x; cs[1][r] = e0.y; cs[2][r] = e1.x; cs[3][r] = e1.y;
            }
            #pragma unroll
            for (int cc = 0; cc < 4; cc++) {
                int c = c0 + cc;
                float* dst = (c < KD) ? (kT + c * TT + j0) : (vT + (c - KD) * TT + j0);
                *(float4*)dst       = make_float4(cs[cc][0], cs[cc][1], cs[cc][2], cs[cc][3]);
                *(float4*)(dst + 4) = make_float4(cs[cc][4], cs[cc][5], cs[cc][6], cs[cc][7]);
            }
        }

        // ---- Q projection (threads 0-127); concat-tail copy (128-255, h==0)
        if (t < 128) {
            const int rg = t & 15, cg = t >> 4;
            const int i0 = rg * 4, c0 = cg * 4;
            ull acc[4][2];
            #pragma unroll
            for (int r = 0; r < 4; r++) { acc[r][0] = 0ull; acc[r][1] = 0ull; }

            #pragma unroll 8
            for (int k = 0; k < KD; k++) {
                float4 a0 = *(const float4*)&sT[k * 132 + ig0 + i0];
                ulonglong2 b2v = *(const ulonglong2*)&swq[k * 68 + c0];
                ull ad;
                ad = pack2(a0.x, a0.x); acc[0][0] = ffma2(ad, b2v.x, acc[0][0]); acc[0][1] = ffma2(ad, b2v.y, acc[0][1]);
                ad = pack2(a0.y, a0.y); acc[1][0] = ffma2(ad, b2v.x, acc[1][0]); acc[1][1] = ffma2(ad, b2v.y, acc[1][1]);
                ad = pack2(a0.z, a0.z); acc[2][0] = ffma2(ad, b2v.x, acc[2][0]); acc[2][1] = ffma2(ad, b2v.y, acc[2][1]);
                ad = pack2(a0.w, a0.w); acc[3][0] = ffma2(ad, b2v.x, acc[3][0]); acc[3][1] = ffma2(ad, b2v.y, acc[3][1]);
            }
            float qs[4][4];
            #pragma unroll
            for (int r = 0; r < 4; r++) {
                float2 e0 = unpack2(acc[r][0]), e1 = unpack2(acc[r][1]);
                qs[0][r] = e0.x; qs[1][r] = e0.y; qs[2][r] = e1.x; qs[3][r] = e1.y;
            }
            #pragma unroll
            for (int cc = 0; cc < 4; cc++)
                *(float4*)&qT[(cc + c0) * 64 + i0] =
                    make_float4(qs[cc][0], qs[cc][1], qs[cc][2], qs[cc][3]);
        } else if (h == 0) {
            int n = t - 128;
            #pragma unroll
            for (int u = 0; u < 4; u++) {
                int m = n + u * 128;
                int row = m >> 3, c = (m & 7) * 4;
                size_t gr = (size_t)b * TT + ig0 + row;
                float4 v = *(const float4*)(state + gr * KD + c);
                *(float4*)(g_act + gr * DINP + 4 * KD + c) = v;
            }
        }
        __syncthreads();

        // ---- GEMM1: S^T[j][i] = K[j]·Q[i]; tile 8i x 4j
        {
            const int ig = t >> 5, jg = t & 31;
            const int i0 = ig * 8, j0 = jg * 4;
            ull acc[4][4];
            #pragma unroll
            for (int c = 0; c < 4; c++)
                #pragma unroll
                for (int p = 0; p < 4; p++) acc[c][p] = 0ull;

            #pragma unroll 4
            for (int kk = 0; kk < KD; kk++) {
                const float* qrow = qT + kk * 64 + i0;
                ulonglong2 a01 = *(const ulonglong2*)qrow;
                ulonglong2 a23 = *(const ulonglong2*)(qrow + 4);
                float4 bj = *(const float4*)(kT + kk * TT + j0);
                ull bd;
                bd = pack2(bj.x, bj.x);
                acc[0][0] = ffma2(bd, a01.x, acc[0][0]); acc[0][1] = ffma2(bd, a01.y, acc[0][1]);
                acc[0][2] = ffma2(bd, a23.x, acc[0][2]); acc[0][3] = ffma2(bd, a23.y, acc[0][3]);
                bd = pack2(bj.y, bj.y);
                acc[1][0] = ffma2(bd, a01.x, acc[1][0]); acc[1][1] = ffma2(bd, a01.y, acc[1][1]);
                acc[1][2] = ffma2(bd, a23.x, acc[1][2]); acc[1][3] = ffma2(bd, a23.y, acc[1][3]);
                bd = pack2(bj.z, bj.z);
                acc[2][0] = ffma2(bd, a01.x, acc[2][0]); acc[2][1] = ffma2(bd, a01.y, acc[2][1]);
                acc[2][2] = ffma2(bd, a23.x, acc[2][2]); acc[2][3] = ffma2(bd, a23.y, acc[2][3]);
                bd = pack2(bj.w, bj.w);
                acc[3][0] = ffma2(bd, a01.x, acc[3][0]); acc[3][1] = ffma2(bd, a01.y, acc[3][1]);
                acc[3][2] = ffma2(bd, a23.x, acc[3][2]); acc[3][3] = ffma2(bd, a23.y, acc[3][3]);
            }

            __syncthreads();    // proj staging consumed before P overwrites it
            #pragma unroll
            for (int c = 0; c < 4; c++) {
                int jglob = j0 + c;
                int rd = jglob - ig0 - i0;
                if (rd >= 0 && rd < 8) {
                    int p = rd >> 1, hi = rd & 1;
                    float2 v = unpack2(acc[c][p]);
                    if (hi) v.y = -1e30f; else v.x = -1e30f;
                    acc[c][p] = pack2(v.x, v.y);
                }
                ull* dst = (ull*)&P[jglob * 64 + i0];
                dst[0] = acc[c][0]; dst[1] = acc[c][1];
                dst[2] = acc[c][2]; dst[3] = acc[c][3];
            }
        }
        __syncthreads();

        // ---- softmax (over j) on P, in place
        {
            const float scale = 0.17677669529663687f;   // 1/sqrt(32)
            const int i = t & 63, q = t >> 6;
            float mx = -1e30f;
            #pragma unroll 8
            for (int jj = 0; jj < 32; jj++)
                mx = fmaxf(mx, P[(q * 32 + jj) * 64 + i]);
            s_mx[q * 64 + i] = mx;
            __syncthreads();
            float m = fmaxf(fmaxf(s_mx[0 * 64 + i], s_mx[1 * 64 + i]),
                            fmaxf(s_mx[2 * 64 + i], s_mx[3 * 64 + i]));
            float sum = 0.f;
            #pragma unroll 8
            for (int jj = 0; jj < 32; jj++) {
                int idx = (q * 32 + jj) * 64 + i;
                float e = __expf((P[idx] - m) * scale);
                P[idx] = e;
                sum += e;
            }
            s_sm[q * 64 + i] = sum;
        }
        __syncthreads();
        if (t < 64)
            s_inv[t] = 1.f / (s_sm[0 * 64 + t] + s_sm[1 * 64 + t] +
                              s_sm[2 * 64 + t] + s_sm[3 * 64 + t]);
        __syncthreads();

        // ---- GEMM2: O[i][d] = sum_j P[j][i] * V[j][d]; tile 4i x 2d
        {
            const int ig = t & 15, dg = t >> 4;
            const int i0 = ig * 4, d0 = dg * 2;
            ull o[2][2];
            o[0][0] = 0ull; o[0][1] = 0ull; o[1][0] = 0ull; o[1][1] = 0ull;
            const float* v0p = vT + d0 * TT;
            const float* v1p = v0p + TT;

            for (int j = 0; j < TT; j += 4) {
                float4 v40 = *(const float4*)(v0p + j);
                float4 v41 = *(const float4*)(v1p + j);
                float va0[4] = {v40.x, v40.y, v40.z, v40.w};
                float va1[4] = {v41.x, v41.y, v41.z, v41.w};
                #pragma unroll
                for (int u = 0; u < 4; u++) {
                    ulonglong2 a = *(const ulonglong2*)&P[(j + u) * 64 + i0];
                    ull vd0 = pack2(va0[u], va0[u]);
                    ull vd1 = pack2(va1[u], va1[u]);
                    o[0][0] = ffma2(vd0, a.x, o[0][0]); o[0][1] = ffma2(vd0, a.y, o[0][1]);
                    o[1][0] = ffma2(vd1, a.x, o[1][0]); o[1][1] = ffma2(vd1, a.y, o[1][1]);
                }
            }

            #pragma unroll
            for (int p = 0; p < 2; p++) {
                float2 e0 = unpack2(o[0][p]);
                float2 e1 = unpack2(o[1][p]);
                float r0v[2] = {e0.x, e0.y};
                float r1v[2] = {e1.x, e1.y};
                #pragma unroll
                for (int u = 0; u < 2; u++) {
                    int il = i0 + p * 2 + u;
                    int iglob = ig0 + il;
                    float inv = s_inv[il];
                    float out0 = r0v[u] * inv - v0p[iglob];
                    float out1 = r1v[u] * inv - v1p[iglob];
                    *(float2*)(g_act + ((size_t)b * TT + iglob) * DINP + h * KD + d0)
                        = make_float2(out0, out1);
                }
            }
        }

        // ---- publish: all g_act writes for this (b,h,ihalf) are done
        __syncthreads();
        __threadfence();
        if (t == 0) atomicAdd(&g_flag[b], 1);
    }

    // =======================================================================
    // PHASE B: dynamic-queue MLP items (32 rows each, 128 items)
    // =======================================================================
    {
        float* s_a  = sm;                                   // [32][160]
        float* s_h1 = sm + MROWS * DINP;                    // [32][256]
        float* s_w  = sm + MROWS * DINP + MROWS * HIDN;     // ring [4][2048]
        const uint32_t wsm = (uint32_t)__cvta_generic_to_shared(s_w);

        const int wrp  = t >> 5;
        const int lane = t & 31;
        const int c0 = (wrp & 1) * 128 + lane * 4;
        const int r0 = (wrp >> 1) * 8;

        #define PANEL_SRC(i) (((i) < NCH1) ? (W1 + (size_t)(i) * PANF) \
                                           : (W2 + (size_t)((i) - NCH1) * PANF))

        while (true) {
            if (t == 0) s_idx = atomicAdd(&g_qhead, 1);
            __syncthreads();
            const int item = s_idx;
            if (item >= 128) break;
            const int rbase = item * MROWS;
            const int bb = item >> 2;                       // 4 items per batch

            // wait for all 8 attn producers of batch bb
            if (t == 0) {
                while (*((volatile int*)&g_flag[bb]) < 8) __nanosleep(64);
            }
            __syncthreads();
            __threadfence();

            // prologue: panels 0..2 into ring; stage act tile
            #pragma unroll
            for (int pidx = 0; pidx < NRING - 1; pidx++) {
                const float* src = PANEL_SRC(pidx);
                const uint32_t dstb = wsm + (uint32_t)((pidx & (NRING - 1)) * PANF) * 4;
                #pragma unroll
                for (int u = 0; u < 2; u++)
                    cpa16(dstb + (uint32_t)(t + u * 256) * 16, src + (size_t)(t + u * 256) * 4);
                cpa_commit();
            }
            {
                const float4* src = (const float4*)(g_act + (size_t)rbase * DINP);
                float4* dst = (float4*)s_a;
                #pragma unroll
                for (int n = t; n < MROWS * DINP / 4; n += 256) dst[n] = src[n];
            }

            ull acc[8][2];
            {
                float4 bl = *(const float4*)(b1 + c0);
                #pragma unroll
                for (int r = 0; r < 8; r++) {
                    acc[r][0] = pack2(bl.x, bl.y);
                    acc[r][1] = pack2(bl.z, bl.w);
                }
            }

            for (int ch = 0; ch < NCHT; ch++) {
                cpa_wait<NRING - 2>();
                __syncthreads();
                if (ch + NRING - 1 < NCHT) {
                    const int pidx = ch + NRING - 1;
                    const float* src = PANEL_SRC(pidx);
                    const uint32_t dstb = wsm + (uint32_t)((pidx & (NRING - 1)) * PANF) * 4;
                    #pragma unroll
                    for (int u = 0; u < 2; u++)
                        cpa16(dstb + (uint32_t)(t + u * 256) * 16, src + (size_t)(t + u * 256) * 4);
                }
                cpa_commit();

                if (ch == NCH1) {           // phase boundary: relu -> s_h1
                    #pragma unroll
                    for (int r = 0; r < 8; r++) {
                        float2 p0 = unpack2(acc[r][0]), p1 = unpack2(acc[r][1]);
                        *(float4*)&s_h1[(r0 + r) * HIDN + c0] =
                            make_float4(fmaxf(p0.x, 0.f), fmaxf(p0.y, 0.f),
                                        fmaxf(p1.x, 0.f), fmaxf(p1.y, 0.f));
                    }
                    float4 bl = *(const float4*)(b2 + c0);
                    #pragma unroll
                    for (int r = 0; r < 8; r++) {
                        acc[r][0] = pack2(bl.x, bl.y);
                        acc[r][1] = pack2(bl.z, bl.w);
                    }
                    __syncthreads();
                }

                const float* wp = s_w + (ch & (NRING - 1)) * PANF;
                const bool ph1 = (ch < NCH1);
                const float* ap = ph1 ? s_a : s_h1;
                const int pitch = ph1 ? DINP : HIDN;
                const int kg0 = (ph1 ? ch : (ch - NCH1)) * CKP;

                #pragma unroll
                for (int half = 0; half < 2; half++) {
                    float4 areg[8];
                    #pragma unroll
                    for (int r = 0; r < 8; r++)
                        areg[r] = *(const float4*)&ap[(r0 + r) * pitch + kg0 + half * 4];
                    #pragma unroll
                    for (int k2 = 0; k2 < 4; k2++) {
                        ulonglong2 w01 = *(const ulonglong2*)(wp + (half * 4 + k2) * HIDN + c0);
                        #pragma unroll
                        for (int r = 0; r < 8; r++) {
                            float av = (k2 == 0) ? areg[r].x : (k2 == 1) ? areg[r].y
                                     : (k2 == 2) ? areg[r].z : areg[r].w;
                            ull ad = pack2(av, av);
                            acc[r][0] = ffma2(ad, w01.x, acc[r][0]);
                            acc[r][1] = ffma2(ad, w01.y, acc[r][1]);
                        }
                    }
                }
            }

            // relu + dot with my 4-col Wo slice; shfl + 2-way smem combine
            float4 wl = *(const float4*)(Wo + c0);
            float p[8];
            #pragma unroll
            for (int r = 0; r < 8; r++) {
                float2 p0 = unpack2(acc[r][0]), p1 = unpack2(acc[r][1]);
                float s = 0.f;
                s = fmaf(fmaxf(p0.x, 0.f), wl.x, s);
                s = fmaf(fmaxf(p0.y, 0.f), wl.y, s);
                s = fmaf(fmaxf(p1.x, 0.f), wl.z, s);
                s = fmaf(fmaxf(p1.y, 0.f), wl.w, s);
                p[r] = s;
            }
            #pragma unroll
            for (int off = 16; off; off >>= 1) {
                #pragma unroll
                for (int r = 0; r < 8; r++)
                    p[r] += __shfl_down_sync(0xffffffffu, p[r], off);
            }
            if (lane == 0) {
                #pragma unroll
                for (int r = 0; r < 8; r++)
                    s_red[r0 + r][wrp & 1] = p[r];
            }
            __syncthreads();
            if (t < MROWS)
                out[rbase + t] = s_red[t][0] + s_red[t][1] + bo[0];
            __syncthreads();        // s_red consumed before next item reuses it
        }
    }

    // ---- replay reset: last CTA to exit zeroes the sync state
    if (t == 0) {
        int d = atomicAdd(&g_done, 1);
        if (d == (int)gridDim.x - 1) {
            #pragma unroll
            for (int i = 0; i < BB; i++) g_flag[i] = 0;
            g_qhead = 0;
            __threadfence();
            g_done = 0;
        }
    }
}

// ---------------------------------------------------------------------------
extern "C" void kernel_launch(void* const* d_in, const int* in_sizes, int n_in,
                              void* d_out, int out_size)
{
    (void)in_sizes; (void)n_in; (void)out_size;
    const float* state = (const float*)d_in[0];
    const float* Wq    = (const float*)d_in[1];
    const float* Wk    = (const float*)d_in[2];
    const float* Wv    = (const float*)d_in[3];
    const float* W1    = (const float*)d_in[4];
    const float* b1    = (const float*)d_in[5];
    const float* W2    = (const float*)d_in[6];
    const float* b2    = (const float*)d_in[7];
    const float* Wo    = (const float*)d_in[8];
    const float* bo    = (const float*)d_in[9];
    float* out = (float*)d_out;

    cudaFuncSetAttribute(fused_kernel,
                         cudaFuncAttributeMaxDynamicSharedMemorySize,
                         FUSED_SMEM_BYTES);
    fused_kernel<<<BB * HH * 2, 256, FUSED_SMEM_BYTES>>>(
        state, Wq, Wk, Wv, W1, b1, W2, b2, Wo, bo, out);
}

// round 15
// speedup vs baseline: 1.1861x; 1.1861x over previous
#include <cuda_runtime.h>
#include <cstdint>

#define BB   32
#define TT   128
#define KD   32
#define HH   4
#define DINP 160
#define HIDN 256

// Scratch (static device global; no allocation).
__device__ float g_act[BB * TT * DINP];     // [x | state]  4096 x 160

typedef unsigned long long ull;

__device__ __forceinline__ ull ffma2(ull a, ull b, ull c) {
    ull d;
    asm("fma.rn.f32x2 %0, %1, %2, %3;" : "=l"(d) : "l"(a), "l"(b), "l"(c));
    return d;
}
__device__ __forceinline__ ull pack2(float x, float y) {
    ull r;
    asm("mov.b64 %0, {%1, %2};" : "=l"(r) : "f"(x), "f"(y));
    return r;
}
__device__ __forceinline__ float2 unpack2(ull v) {
    float x, y;
    asm("mov.b64 {%0, %1}, %2;" : "=f"(x), "=f"(y) : "l"(v));
    return make_float2(x, y);
}

// ---------------------------------------------------------------------------
// Fused attention smem layout (floats). P aliases the proj staging region.
// ---------------------------------------------------------------------------
#define OFF_ST    0            // stateT [32][pitch 132]       4224
#define OFF_WQ    4224         // WqT-slice [32][pitch 68]     2176
#define OFF_WKV   6400         // Wk|Wv slice [32][pitch 68]   2176  (end 8576)
#define OFF_P     0            // P [128][64]                  8192  (alias)
#define OFF_KT    8576         // kT [32][128]                 4096
#define OFF_VT    12672        // vT [32][128]                 4096
#define OFF_QT    16768        // qT [32][64]                  2048
#define OFF_MX    18816        // [4][64]
#define OFF_SM    19072        // [4][64]
#define OFF_INV   19328        // [64]
#define ATTN_SMEM_FLOATS 19392
#define ATTN_SMEM_BYTES  (ATTN_SMEM_FLOATS * 4)

// ---------------------------------------------------------------------------
// Kernel 1 (fused QKV-proj + masked attention), 64 query rows of one (b,h).
// grid 256 = (b, h, ihalf), 256 threads, 2 CTA/SM.  (byte-identical to R8)
// ---------------------------------------------------------------------------
__global__ void __launch_bounds__(256, 2) attn_kernel(
    const float* __restrict__ state,
    const float* __restrict__ Wq,
    const float* __restrict__ Wk,
    const float* __restrict__ Wv)
{
    extern __shared__ float sm[];
    const int bx = blockIdx.x;
    const int b = bx >> 3, h = (bx >> 1) & 3, ihalf = bx & 1;
    const int t = threadIdx.x;
    const int ig0 = ihalf * 64;

    float* sT    = sm + OFF_ST;
    float* swq   = sm + OFF_WQ;
    float* swkv  = sm + OFF_WKV;
    float* P     = sm + OFF_P;
    float* kT    = sm + OFF_KT;
    float* vT    = sm + OFF_VT;
    float* qT    = sm + OFF_QT;
    float* s_mx  = sm + OFF_MX;
    float* s_sm  = sm + OFF_SM;
    float* s_inv = sm + OFF_INV;

    // ---- stage stateT [c][j] (pitch 132) and weight slices (pitch 68)
    {
        int r = t >> 1, c0 = (t & 1) * 16;
        const float4* p = (const float4*)(state + ((size_t)b * TT + r) * KD + c0);
        #pragma unroll
        for (int w = 0; w < 4; w++) {
            float4 v = p[w];
            sT[(c0 + 4 * w + 0) * 132 + r] = v.x;
            sT[(c0 + 4 * w + 1) * 132 + r] = v.y;
            sT[(c0 + 4 * w + 2) * 132 + r] = v.z;
            sT[(c0 + 4 * w + 3) * 132 + r] = v.w;
        }
    }
    {
        int r = t >> 3, q = t & 7;      // 32 rows x 8 float4-chunks of the 32-col slice
        size_t src = (size_t)r * (KD * HH) + h * KD + q * 4;
        *(float4*)&swq[r * 68 + q * 4]        = *(const float4*)(Wq + src);
        *(float4*)&swkv[r * 68 + q * 4]       = *(const float4*)(Wk + src);
        *(float4*)&swkv[r * 68 + 32 + q * 4]  = *(const float4*)(Wv + src);
    }
    __syncthreads();

    // ---- KV projection: 128 rows x 64 cols (K|V), tile 8r x 4c per thread
    {
        const int rg = t & 15, cg = t >> 4;
        const int j0 = rg * 8, c0 = cg * 4;
        ull acc[8][2];
        #pragma unroll
        for (int r = 0; r < 8; r++) { acc[r][0] = 0ull; acc[r][1] = 0ull; }

        #pragma unroll 8
        for (int k = 0; k < KD; k++) {
            float4 a0 = *(const float4*)&sT[k * 132 + j0];
            float4 a1 = *(const float4*)&sT[k * 132 + j0 + 4];
            ulonglong2 b2 = *(const ulonglong2*)&swkv[k * 68 + c0];
            ull ad;
            ad = pack2(a0.x, a0.x); acc[0][0] = ffma2(ad, b2.x, acc[0][0]); acc[0][1] = ffma2(ad, b2.y, acc[0][1]);
            ad = pack2(a0.y, a0.y); acc[1][0] = ffma2(ad, b2.x, acc[1][0]); acc[1][1] = ffma2(ad, b2.y, acc[1][1]);
            ad = pack2(a0.z, a0.z); acc[2][0] = ffma2(ad, b2.x, acc[2][0]); acc[2][1] = ffma2(ad, b2.y, acc[2][1]);
            ad = pack2(a0.w, a0.w); acc[3][0] = ffma2(ad, b2.x, acc[3][0]); acc[3][1] = ffma2(ad, b2.y, acc[3][1]);
            ad = pack2(a1.x, a1.x); acc[4][0] = ffma2(ad, b2.x, acc[4][0]); acc[4][1] = ffma2(ad, b2.y, acc[4][1]);
            ad = pack2(a1.y, a1.y); acc[5][0] = ffma2(ad, b2.x, acc[5][0]); acc[5][1] = ffma2(ad, b2.y, acc[5][1]);
            ad = pack2(a1.z, a1.z); acc[6][0] = ffma2(ad, b2.x, acc[6][0]); acc[6][1] = ffma2(ad, b2.y, acc[6][1]);
            ad = pack2(a1.w, a1.w); acc[7][0] = ffma2(ad, b2.x, acc[7][0]); acc[7][1] = ffma2(ad, b2.y, acc[7][1]);
        }

        float cs[4][8];
        #pragma unroll
        for (int r = 0; r < 8; r++) {
            float2 e0 = unpack2(acc[r][0]), e1 = unpack2(acc[r][1]);
            cs[0][r] = e0.x; cs[1][r] = e0.y; cs[2][r] = e1.x; cs[3][r] = e1.y;
        }
        #pragma unroll
        for (int cc = 0; cc < 4; cc++) {
            int c = c0 + cc;
            float* dst = (c < KD) ? (kT + c * TT + j0) : (vT + (c - KD) * TT + j0);
            *(float4*)dst       = make_float4(cs[cc][0], cs[cc][1], cs[cc][2], cs[cc][3]);
            *(float4*)(dst + 4) = make_float4(cs[cc][4], cs[cc][5], cs[cc][6], cs[cc][7]);
        }
    }

    // ---- Q projection (threads 0-127); concat-tail copy (threads 128-255, h==0)
    if (t < 128) {
        const int rg = t & 15, cg = t >> 4;
        const int i0 = rg * 4, c0 = cg * 4;
        ull acc[4][2];
        #pragma unroll
        for (int r = 0; r < 4; r++) { acc[r][0] = 0ull; acc[r][1] = 0ull; }

        #pragma unroll 8
        for (int k = 0; k < KD; k++) {
            float4 a0 = *(const float4*)&sT[k * 132 + ig0 + i0];
            ulonglong2 b2 = *(const ulonglong2*)&swq[k * 68 + c0];
            ull ad;
            ad = pack2(a0.x, a0.x); acc[0][0] = ffma2(ad, b2.x, acc[0][0]); acc[0][1] = ffma2(ad, b2.y, acc[0][1]);
            ad = pack2(a0.y, a0.y); acc[1][0] = ffma2(ad, b2.x, acc[1][0]); acc[1][1] = ffma2(ad, b2.y, acc[1][1]);
            ad = pack2(a0.z, a0.z); acc[2][0] = ffma2(ad, b2.x, acc[2][0]); acc[2][1] = ffma2(ad, b2.y, acc[2][1]);
            ad = pack2(a0.w, a0.w); acc[3][0] = ffma2(ad, b2.x, acc[3][0]); acc[3][1] = ffma2(ad, b2.y, acc[3][1]);
        }
        float qs[4][4];
        #pragma unroll
        for (int r = 0; r < 4; r++) {
            float2 e0 = unpack2(acc[r][0]), e1 = unpack2(acc[r][1]);
            qs[0][r] = e0.x; qs[1][r] = e0.y; qs[2][r] = e1.x; qs[3][r] = e1.y;
        }
        #pragma unroll
        for (int cc = 0; cc < 4; cc++)
            *(float4*)&qT[(c0 + cc) * 64 + i0] =
                make_float4(qs[cc][0], qs[cc][1], qs[cc][2], qs[cc][3]);
    } else if (h == 0) {
        int n = t - 128;                           // 512 float4s, 4 per thread
        #pragma unroll
        for (int u = 0; u < 4; u++) {
            int m = n + u * 128;
            int row = m >> 3, c = (m & 7) * 4;
            size_t gr = (size_t)b * TT + ig0 + row;
            float4 v = *(const float4*)(state + gr * KD + c);
            *(float4*)(g_act + gr * DINP + 4 * KD + c) = v;
        }
    }
    __syncthreads();

    // ---- GEMM1: S^T[j][i] = K[j]·Q[i]; tile 8i x 4j (reads smem kT/qT)
    {
        const int ig = t >> 5, jg = t & 31;
        const int i0 = ig * 8, j0 = jg * 4;
        ull acc[4][4];
        #pragma unroll
        for (int c = 0; c < 4; c++)
            #pragma unroll
            for (int p = 0; p < 4; p++) acc[c][p] = 0ull;

        #pragma unroll 4
        for (int kk = 0; kk < KD; kk++) {
            const float* qrow = qT + kk * 64 + i0;
            ulonglong2 a01 = *(const ulonglong2*)qrow;
            ulonglong2 a23 = *(const ulonglong2*)(qrow + 4);
            float4 bj = *(const float4*)(kT + kk * TT + j0);
            ull bd;
            bd = pack2(bj.x, bj.x);
            acc[0][0] = ffma2(bd, a01.x, acc[0][0]); acc[0][1] = ffma2(bd, a01.y, acc[0][1]);
            acc[0][2] = ffma2(bd, a23.x, acc[0][2]); acc[0][3] = ffma2(bd, a23.y, acc[0][3]);
            bd = pack2(bj.y, bj.y);
            acc[1][0] = ffma2(bd, a01.x, acc[1][0]); acc[1][1] = ffma2(bd, a01.y, acc[1][1]);
            acc[1][2] = ffma2(bd, a23.x, acc[1][2]); acc[1][3] = ffma2(bd, a23.y, acc[1][3]);
            bd = pack2(bj.z, bj.z);
            acc[2][0] = ffma2(bd, a01.x, acc[2][0]); acc[2][1] = ffma2(bd, a01.y, acc[2][1]);
            acc[2][2] = ffma2(bd, a23.x, acc[2][2]); acc[2][3] = ffma2(bd, a23.y, acc[2][3]);
            bd = pack2(bj.w, bj.w);
            acc[3][0] = ffma2(bd, a01.x, acc[3][0]); acc[3][1] = ffma2(bd, a01.y, acc[3][1]);
            acc[3][2] = ffma2(bd, a23.x, acc[3][2]); acc[3][3] = ffma2(bd, a23.y, acc[3][3]);
        }

        __syncthreads();    // proj staging fully consumed before P overwrites it
        #pragma unroll
        for (int c = 0; c < 4; c++) {
            int jglob = j0 + c;
            int rd = jglob - ig0 - i0;          // diag position within my 8 i's
            if (rd >= 0 && rd < 8) {
                int p = rd >> 1, hi = rd & 1;
                float2 v = unpack2(acc[c][p]);
                if (hi) v.y = -1e30f; else v.x = -1e30f;
                acc[c][p] = pack2(v.x, v.y);
            }
            ull* dst = (ull*)&P[jglob * 64 + i0];
            dst[0] = acc[c][0]; dst[1] = acc[c][1];
            dst[2] = acc[c][2]; dst[3] = acc[c][3];
        }
    }
    __syncthreads();

    // ---- softmax (over j) on P, in place
    {
        const float scale = 0.17677669529663687f;   // 1/sqrt(32)
        const int i = t & 63, q = t >> 6;
        float mx = -1e30f;
        #pragma unroll 8
        for (int jj = 0; jj < 32; jj++)
            mx = fmaxf(mx, P[(q * 32 + jj) * 64 + i]);
        s_mx[q * 64 + i] = mx;
        __syncthreads();
        float m = fmaxf(fmaxf(s_mx[0 * 64 + i], s_mx[1 * 64 + i]),
                        fmaxf(s_mx[2 * 64 + i], s_mx[3 * 64 + i]));
        float sum = 0.f;
        #pragma unroll 8
        for (int jj = 0; jj < 32; jj++) {
            int idx = (q * 32 + jj) * 64 + i;
            float e = __expf((P[idx] - m) * scale);
            P[idx] = e;
            sum += e;
        }
        s_sm[q * 64 + i] = sum;
    }
    __syncthreads();
    if (t < 64)
        s_inv[t] = 1.f / (s_sm[0 * 64 + t] + s_sm[1 * 64 + t] +
                          s_sm[2 * 64 + t] + s_sm[3 * 64 + t]);
    __syncthreads();

    // ---- GEMM2: O[i][d] = sum_j P[j][i] * V[j][d]; tile 4i x 2d (smem vT)
    {
        const int ig = t & 15, dg = t >> 4;
        const int i0 = ig * 4, d0 = dg * 2;
        ull o[2][2];
        o[0][0] = 0ull; o[0][1] = 0ull; o[1][0] = 0ull; o[1][1] = 0ull;
        const float* v0p = vT + d0 * TT;
        const float* v1p = v0p + TT;

        for (int j = 0; j < TT; j += 4) {
            float4 v40 = *(const float4*)(v0p + j);
            float4 v41 = *(const float4*)(v1p + j);
            float va0[4] = {v40.x, v40.y, v40.z, v40.w};
            float va1[4] = {v41.x, v41.y, v41.z, v41.w};
            #pragma unroll
            for (int u = 0; u < 4; u++) {
                ulonglong2 a = *(const ulonglong2*)&P[(j + u) * 64 + i0];
                ull vd0 = pack2(va0[u], va0[u]);
                ull vd1 = pack2(va1[u], va1[u]);
                o[0][0] = ffma2(vd0, a.x, o[0][0]); o[0][1] = ffma2(vd0, a.y, o[0][1]);
                o[1][0] = ffma2(vd1, a.x, o[1][0]); o[1][1] = ffma2(vd1, a.y, o[1][1]);
            }
        }

        #pragma unroll
        for (int p = 0; p < 2; p++) {
            float2 e0 = unpack2(o[0][p]);
            float2 e1 = unpack2(o[1][p]);
            float r0[2] = {e0.x, e0.y};
            float r1[2] = {e1.x, e1.y};
            #pragma unroll
            for (int u = 0; u < 2; u++) {
                int il = i0 + p * 2 + u;
                int iglob = ig0 + il;
                float inv = s_inv[il];
                float out0 = r0[u] * inv - v0p[iglob];
                float out1 = r1[u] * inv - v1p[iglob];
                *(float2*)(g_act + ((size_t)b * TT + iglob) * DINP + h * KD + d0)
                    = make_float2(out0, out1);
            }
        }
    }
}

// ---------------------------------------------------------------------------
// Kernel 2 (fused MLP): 32 rows/block, grid 128 (single wave), 256 threads.
// Warp w = (colhalf w&1, rowgroup w>>1): tile 8 rows x 4 cols.
// W stays in REGISTERS: each thread double-buffers its 8xfloat4 W-panel
// slice via coalesced LDG (L2-resident W1/W2). Two explicit phase loops
// (simple codegen); zero in-loop barriers; crossbar carries only
// a-broadcasts. Dynamic smem: s_a 20KB + s_h1 32KB = 52KB.
// ---------------------------------------------------------------------------
#define CKP   8
#define MROWS 32
#define NCH1  (DINP / CKP)                    // 20
#define NCH2  (HIDN / CKP)                    // 32
#define MLP_SMEM_BYTES ((MROWS * DINP + MROWS * HIDN) * 4)

// one chunk of FFMA2 work: a from smem (pitch fixed per call site), W in regs
template <int PITCH>
__device__ __forceinline__ void mlp_chunk(
    const float* ap, int r0, int kg0, const float4* wb, ull acc[8][2])
{
    #pragma unroll
    for (int half = 0; half < 2; half++) {
        float4 areg[8];
        #pragma unroll
        for (int r = 0; r < 8; r++)
            areg[r] = *(const float4*)&ap[(r0 + r) * PITCH + kg0 + half * 4];
        #pragma unroll
        for (int k2 = 0; k2 < 4; k2++) {
            ulonglong2 w01 = *(const ulonglong2*)&wb[half * 4 + k2];
            #pragma unroll
            for (int r = 0; r < 8; r++) {
                float av = (k2 == 0) ? areg[r].x : (k2 == 1) ? areg[r].y
                         : (k2 == 2) ? areg[r].z : areg[r].w;
                ull ad = pack2(av, av);
                acc[r][0] = ffma2(ad, w01.x, acc[r][0]);
                acc[r][1] = ffma2(ad, w01.y, acc[r][1]);
            }
        }
    }
}

__device__ __forceinline__ void ldw(float4* dst, const float* src)
{
    #pragma unroll
    for (int kk = 0; kk < CKP; kk++)
        dst[kk] = *(const float4*)(src + (size_t)kk * HIDN);
}

__global__ void __launch_bounds__(256, 1) mlp_kernel(
    const float* __restrict__ W1, const float* __restrict__ b1,
    const float* __restrict__ W2, const float* __restrict__ b2,
    const float* __restrict__ Wo, const float* __restrict__ bo,
    float* __restrict__ out)
{
    extern __shared__ float smf[];
    float* s_a  = smf;                                  // [32][160]
    float* s_h1 = smf + MROWS * DINP;                   // [32][256]
    __shared__ float s_red[MROWS][2];

    const int rbase = blockIdx.x * MROWS;
    const int t = threadIdx.x;
    const int wrp  = t >> 5;
    const int lane = t & 31;
    const int c0 = (wrp & 1) * 128 + lane * 4;          // 4 cols in my 128-col half
    const int r0 = (wrp >> 1) * 8;                      // 8 rows

    // stage act tile
    {
        const float4* src = (const float4*)(g_act + (size_t)rbase * DINP);
        float4* dst = (float4*)s_a;
        #pragma unroll
        for (int n = t; n < MROWS * DINP / 4; n += 256) dst[n] = src[n];
    }

    ull acc[8][2];
    {
        float4 bl = *(const float4*)(b1 + c0);
        #pragma unroll
        for (int r = 0; r < 8; r++) {
            acc[r][0] = pack2(bl.x, bl.y);
            acc[r][1] = pack2(bl.z, bl.w);
        }
    }

    const float* w1p = W1 + c0;     // this thread's 4-col slice base
    const float* w2p = W2 + c0;

    float4 bufA[CKP], bufB[CKP];
    ldw(bufA, w1p);                 // chunk 0
    __syncthreads();                // s_a staged

    // ---- phase 1: 20 chunks over W1 (x2 unrolled ping-pong)
    #pragma unroll 1
    for (int ch = 0; ch < NCH1; ch += 2) {
        ldw(bufB, w1p + (size_t)(ch + 1) * CKP * HIDN);
        mlp_chunk<DINP>(s_a, r0, ch * CKP, bufA, acc);
        if (ch + 2 < NCH1) ldw(bufA, w1p + (size_t)(ch + 2) * CKP * HIDN);
        else               ldw(bufA, w2p);                  // W2 chunk 0
        mlp_chunk<DINP>(s_a, r0, (ch + 1) * CKP, bufB, acc);
    }

    // ---- phase boundary: relu -> s_h1, re-init acc with b2
    #pragma unroll
    for (int r = 0; r < 8; r++) {
        float2 p0 = unpack2(acc[r][0]), p1 = unpack2(acc[r][1]);
        *(float4*)&s_h1[(r0 + r) * HIDN + c0] =
            make_float4(fmaxf(p0.x, 0.f), fmaxf(p0.y, 0.f),
                        fmaxf(p1.x, 0.f), fmaxf(p1.y, 0.f));
    }
    {
        float4 bl = *(const float4*)(b2 + c0);
        #pragma unroll
        for (int r = 0; r < 8; r++) {
            acc[r][0] = pack2(bl.x, bl.y);
            acc[r][1] = pack2(bl.z, bl.w);
        }
    }
    __syncthreads();

    // ---- phase 2: 32 chunks over W2 (x2 unrolled ping-pong)
    #pragma unroll 1
    for (int ch = 0; ch < NCH2; ch += 2) {
        ldw(bufB, w2p + (size_t)(ch + 1) * CKP * HIDN);
        mlp_chunk<HIDN>(s_h1, r0, ch * CKP, bufA, acc);
        if (ch + 2 < NCH2) ldw(bufA, w2p + (size_t)(ch + 2) * CKP * HIDN);
        mlp_chunk<HIDN>(s_h1, r0, (ch + 1) * CKP, bufB, acc);
    }

    // ---- relu + dot with my 4-col Wo slice; full-warp shfl covers 128 cols,
    //      then combine the two column-halves via s_red.
    float4 wl = *(const float4*)(Wo + c0);
    float p[8];
    #pragma unroll
    for (int r = 0; r < 8; r++) {
        float2 p0 = unpack2(acc[r][0]), p1 = unpack2(acc[r][1]);
        float s = 0.f;
        s = fmaf(fmaxf(p0.x, 0.f), wl.x, s);
        s = fmaf(fmaxf(p0.y, 0.f), wl.y, s);
        s = fmaf(fmaxf(p1.x, 0.f), wl.z, s);
        s = fmaf(fmaxf(p1.y, 0.f), wl.w, s);
        p[r] = s;
    }
    #pragma unroll
    for (int off = 16; off; off >>= 1) {
        #pragma unroll
        for (int r = 0; r < 8; r++)
            p[r] += __shfl_down_sync(0xffffffffu, p[r], off);
    }
    if (lane == 0) {
        #pragma unroll
        for (int r = 0; r < 8; r++)
            s_red[r0 + r][wrp & 1] = p[r];
    }
    __syncthreads();
    if (t < MROWS)
        out[rbase + t] = s_red[t][0] + s_red[t][1] + bo[0];
}

// ---------------------------------------------------------------------------
extern "C" void kernel_launch(void* const* d_in, const int* in_sizes, int n_in,
                              void* d_out, int out_size)
{
    (void)in_sizes; (void)n_in; (void)out_size;
    const float* state = (const float*)d_in[0];
    const float* Wq    = (const float*)d_in[1];
    const float* Wk    = (const float*)d_in[2];
    const float* Wv    = (const float*)d_in[3];
    const float* W1    = (const float*)d_in[4];
    const float* b1    = (const float*)d_in[5];
    const float* W2    = (const float*)d_in[6];
    const float* b2    = (const float*)d_in[7];
    const float* Wo    = (const float*)d_in[8];
    const float* bo    = (const float*)d_in[9];
    float* out = (float*)d_out;

    cudaFuncSetAttribute(attn_kernel,
                         cudaFuncAttributeMaxDynamicSharedMemorySize,
                         ATTN_SMEM_BYTES);
    cudaFuncSetAttribute(mlp_kernel,
                         cudaFuncAttributeMaxDynamicSharedMemorySize,
                         MLP_SMEM_BYTES);
    attn_kernel<<<BB * HH * 2, 256, ATTN_SMEM_BYTES>>>(state, Wq, Wk, Wv);
    mlp_kernel<<<(BB * TT) / MROWS, 256, MLP_SMEM_BYTES>>>(W1, b1, W2, b2, Wo, bo, out);
}